// round 15
// baseline (speedup 1.0000x reference)
#include <cuda_runtime.h>
#include <cuda_fp16.h>

// ---------------------------------------------------------------------------
// SlatewiseGRU, two-phase:
//  K1 gx_prepass: gx[n*32+t, 384] = x . W_ih^T for ALL timesteps (one big
//     parallel GEMM, fp16 out, memory-bound) -> 201MB __device__ scratch.
//  K2 gru_rec: recurrent loop holds ONLY the h-side GEMM (48 HMMA/warp/step)
//     + epilogue; gx tiles stream in via cp.async double-buffered ring.
// Numerics = R12 (single fp16 planes, fp32 acc, MUFU.TANH, h state hi+lo)
// + gx fp16 rounding (5th calibrated ~2e-4 source).
// ---------------------------------------------------------------------------

#define DD   128
#define LL   32
#define NSEQ 8192
#define NL   (NSEQ * LL)       // 262144 rows
#define TN   32
#define NTHR 256
#define NCTA (NSEQ / TN)       // 256
#define SMP  136               // h SMEM row stride (fp16); 272 B
#define GXR  392               // gx ring row stride (fp16); 784 B
#define GSTG 400               // prepass stage row stride (fp16); 800 B

// Packed B-fragments: [wt:2 (ih,hh)][kt:8][ntile:48 (gg*16+blk)][lane:32]
__device__ uint2 g_wpack[2 * 8 * 48 * 32];
// gx scratch: [row = n*32+t][384]  fp16  (201 MB)
__device__ unsigned short g_gx[(size_t)NL * 384];

__global__ void prep_weights(const float* __restrict__ W_ih,
                             const float* __restrict__ W_hh) {
    int idx = blockIdx.x * blockDim.x + threadIdx.x;
    if (idx >= 2 * 8 * 48 * 32) return;
    int l  = idx & 31;
    int r  = idx >> 5;
    int nt = r % 48; r /= 48;
    int kt = r % 8;  r /= 8;
    int wt = r;
    const float* W = wt ? W_hh : W_ih;
    int gg = nt / 16, b = nt % 16;
    int j  = gg * 128 + b * 8 + (l >> 2);
    int d0 = kt * 16 + (l & 3) * 2;
    unsigned short e[4];
    #pragma unroll
    for (int q = 0; q < 4; ++q) {
        int d = d0 + (q & 1) + (q >> 1) * 8;
        e[q] = __half_as_ushort(__float2half_rn(W[j * DD + d]));
    }
    uint2 v;
    v.x = (unsigned)e[0] | ((unsigned)e[1] << 16);
    v.y = (unsigned)e[2] | ((unsigned)e[3] << 16);
    g_wpack[idx] = v;
}

__device__ __forceinline__ unsigned pkh(__half a, __half b) {
    return (unsigned)__half_as_ushort(a) | ((unsigned)__half_as_ushort(b) << 16);
}
__device__ __forceinline__ float hlo(unsigned u) {
    return __half2float(__ushort_as_half((unsigned short)(u & 0xffffu)));
}
__device__ __forceinline__ float hhi(unsigned u) {
    return __half2float(__ushort_as_half((unsigned short)(u >> 16)));
}

__device__ __forceinline__ void mma16816(float* c, const unsigned* a, uint2 b) {
    asm volatile(
        "mma.sync.aligned.m16n8k16.row.col.f32.f16.f16.f32 "
        "{%0,%1,%2,%3}, {%4,%5,%6,%7}, {%8,%9}, {%0,%1,%2,%3};\n"
        : "+f"(c[0]), "+f"(c[1]), "+f"(c[2]), "+f"(c[3])
        : "r"(a[0]), "r"(a[1]), "r"(a[2]), "r"(a[3]), "r"(b.x), "r"(b.y));
}

__device__ __forceinline__ void ldsm4(unsigned* r, unsigned addr) {
    asm volatile("ldmatrix.sync.aligned.m8n8.x4.shared.b16 {%0,%1,%2,%3}, [%4];"
                 : "=r"(r[0]), "=r"(r[1]), "=r"(r[2]), "=r"(r[3]) : "r"(addr));
}

__device__ __forceinline__ float tanh_mufu(float x) {
    float y;
    asm("tanh.approx.f32 %0, %1;" : "=f"(y) : "f"(x));
    return y;
}
__device__ __forceinline__ float sigm(float x) {
    return fmaf(tanh_mufu(0.5f * x), 0.5f, 0.5f);
}

// ======================= K1: gx pre-pass ====================================
// CTA: 512 thr / 16 warps, 64 rows of X_all. Warp w -> n8-tiles {w,16+w,32+w}
// (units w*8..w*8+8 of each gate). acc 48 regs. gx staged in SMEM then
// copied out coalesced (16B/thread chunks).
extern __shared__ char smpre[];

__global__ void __launch_bounds__(512, 1)
gx_prepass(const float* __restrict__ item) {
    unsigned short* xt = (unsigned short*)smpre;        // [64][SMP]
    unsigned short* st = xt + 64 * SMP;                 // [64][GSTG]

    const int tid = threadIdx.x;
    const int w   = tid >> 5;   // 0..15
    const int l   = tid & 31;
    const int g   = l >> 2;
    const int tg  = l & 3;
    const size_t rbase = (size_t)blockIdx.x * 64;

    // load 64x128 fp32 -> fp16 plane in SMEM
    #pragma unroll
    for (int i = 0; i < 4; ++i) {
        int idx = tid + i * 512;
        int row = idx >> 5, c4 = (idx & 31) * 4;
        float4 v = *(const float4*)(item + (rbase + row) * DD + c4);
        uint2 hv;
        hv.x = pkh(__float2half_rn(v.x), __float2half_rn(v.y));
        hv.y = pkh(__float2half_rn(v.z), __float2half_rn(v.w));
        *(uint2*)&xt[row * SMP + c4] = hv;
    }
    __syncthreads();

    const int rowsel = l & 15;
    const int halfc  = l >> 4;
    const unsigned xtA = (unsigned)__cvta_generic_to_shared(xt)
                       + (unsigned)((rowsel * SMP + halfc * 8) * 2);

    float acc[3][4][4];
    #pragma unroll
    for (int a0 = 0; a0 < 3; ++a0)
        #pragma unroll
        for (int a1 = 0; a1 < 4; ++a1)
            #pragma unroll
            for (int a2 = 0; a2 < 4; ++a2) acc[a0][a1][a2] = 0.f;

    #pragma unroll
    for (int kt = 0; kt < 8; ++kt) {
        uint2 Bw[3];
        #pragma unroll
        for (int gg = 0; gg < 3; ++gg)
            Bw[gg] = g_wpack[kt * 1536 + (gg * 16 + w) * 32 + l];
        unsigned a[4][4];
        #pragma unroll
        for (int mt = 0; mt < 4; ++mt)
            ldsm4(a[mt], xtA + mt * (16 * SMP * 2) + kt * 32);
        #pragma unroll
        for (int gg = 0; gg < 3; ++gg)
            #pragma unroll
            for (int mt = 0; mt < 4; ++mt)
                mma16816(acc[gg][mt], a[mt], Bw[gg]);
    }

    // stage fp16 gx tile in SMEM
    #pragma unroll
    for (int gg = 0; gg < 3; ++gg)
        #pragma unroll
        for (int mt = 0; mt < 4; ++mt)
            #pragma unroll
            for (int rh = 0; rh < 2; ++rh) {
                int row = mt * 16 + g + rh * 8;
                int col = gg * 128 + w * 8 + tg * 2;
                *(unsigned*)&st[row * GSTG + col] =
                    pkh(__float2half_rn(acc[gg][mt][rh * 2]),
                        __float2half_rn(acc[gg][mt][rh * 2 + 1]));
            }
    __syncthreads();

    // coalesced copy-out: 64 rows x 768 B
    #pragma unroll
    for (int i = 0; i < 6; ++i) {
        int idx = tid + i * 512;
        int row = idx / 48, c = idx % 48;
        uint4 v = *(const uint4*)&st[row * GSTG + c * 8];
        *(uint4*)&g_gx[(rbase + row) * 384 + c * 8] = v;
    }
}

// ======================= K2: recurrent kernel ===============================
extern __shared__ char smrec[];

__global__ void __launch_bounds__(NTHR, 2)
gru_rec(const float* __restrict__ user,   // [N, D]
        const float* __restrict__ b_ih,   // [384]
        const float* __restrict__ b_hh,   // [384]
        const float* __restrict__ W_out,  // [128]
        const float* __restrict__ b_out,  // [1]
        float* __restrict__ out)          // [N, L]
{
    unsigned short* hh   = (unsigned short*)smrec;       // [TN][SMP]
    unsigned short* hl   = hh + TN * SMP;                // [TN][SMP]
    unsigned short* ring = hl + TN * SMP;                // [2][32][GXR]
    float* outb = (float*)(ring + 2 * 32 * GXR);         // [8][32]
    float* Bs   = outb + 8 * TN;                         // [512]

    const int tid = threadIdx.x;
    const int w   = tid >> 5;
    const int l   = tid & 31;
    const int g   = l >> 2;
    const int tg  = l & 3;
    const int nBase = blockIdx.x * TN;

    for (int i = tid; i < 512; i += NTHR) {
        float v;
        if (i < 256)      v = b_ih[i] + b_hh[i];
        else if (i < 384) v = b_ih[i];
        else              v = b_hh[i - 128];
        Bs[i] = v;
    }

    const int rowsel = l & 15;
    const int halfc  = l >> 4;
    const unsigned hhA = (unsigned)__cvta_generic_to_shared(hh)
                       + (unsigned)((rowsel * SMP + halfc * 8) * 2);
    const unsigned ringA = (unsigned)__cvta_generic_to_shared(ring);

    const int ua = w * 16 + tg * 2;       // nt = 0
    const int ub = ua + 8;                // nt = 1
    float2 woA = *(const float2*)(W_out + ua);
    float2 woB = *(const float2*)(W_out + ub);
    const float bo = b_out[0];

    // h0 = user_embs (fp16 hi/lo), owner-thread init
    #pragma unroll
    for (int mt = 0; mt < 2; ++mt)
        #pragma unroll
        for (int rh = 0; rh < 2; ++rh) {
            int row = mt * 16 + g + rh * 8;
            #pragma unroll
            for (int nt = 0; nt < 2; ++nt) {
                int u = (nt ? ub : ua);
                float2 v = *(const float2*)(user + (size_t)(nBase + row) * DD + u);
                __half a0 = __float2half_rn(v.x);
                __half a1 = __float2half_rn(v.y);
                *(unsigned*)&hh[row * SMP + u] = pkh(a0, a1);
                *(unsigned*)&hl[row * SMP + u] =
                    pkh(__float2half_rn(v.x - __half2float(a0)),
                        __float2half_rn(v.y - __half2float(a1)));
            }
        }

    // prologue: load gx(t=0) -> buf0 via cp.async; wait fully
    #pragma unroll
    for (int i = 0; i < 6; ++i) {
        int idx = tid + i * NTHR;
        int row = idx / 48, c = idx % 48;
        unsigned dst = ringA + (unsigned)(row * (GXR * 2) + c * 16);
        const void* src = (const char*)g_gx
            + (((size_t)(nBase + row) * LL + 0) * 384 + c * 8) * 2;
        asm volatile("cp.async.cg.shared.global [%0], [%1], 16;"
                     :: "r"(dst), "l"(src) : "memory");
    }
    asm volatile("cp.async.commit_group;" ::: "memory");
    asm volatile("cp.async.wait_group 0;" ::: "memory");
    __syncthreads();   // h0, biases, gx0 visible

    for (int t = 0; t < LL; ++t) {
        const int s = t & 1;

        __syncthreads();   // barrier A: h(t-1)/outb(t-1) visible;
                           // epilogue(t-1) done reading ring[1-s]

        // ---- prefetch gx(t+1) into ring[1-s] ----
        if (t + 1 < LL) {
            #pragma unroll
            for (int i = 0; i < 6; ++i) {
                int idx = tid + i * NTHR;
                int row = idx / 48, c = idx % 48;
                unsigned dst = ringA + (unsigned)((1 - s) * 32 * (GXR * 2)
                                                  + row * (GXR * 2) + c * 16);
                const void* src = (const char*)g_gx
                    + (((size_t)(nBase + row) * LL + (t + 1)) * 384 + c * 8) * 2;
                asm volatile("cp.async.cg.shared.global [%0], [%1], 16;"
                             :: "r"(dst), "l"(src) : "memory");
            }
            asm volatile("cp.async.commit_group;" ::: "memory");
        }

        // ---- out reduction for step t-1 ----
        if (t > 0 && tid < TN) {
            float sum = bo;
            #pragma unroll
            for (int ww = 0; ww < 8; ++ww) sum += outb[ww * TN + tid];
            out[(size_t)(nBase + tid) * LL + (t - 1)] = sum;
        }

        // ---- h-side GEMM(t): acc slots r,z,nh ----
        float acc[3][2][2][4];
        #pragma unroll
        for (int a0 = 0; a0 < 3; ++a0)
            #pragma unroll
            for (int mt = 0; mt < 2; ++mt)
                #pragma unroll
                for (int nt = 0; nt < 2; ++nt)
                    #pragma unroll
                    for (int q = 0; q < 4; ++q) acc[a0][mt][nt][q] = 0.f;

        #pragma unroll
        for (int kt = 0; kt < 8; ++kt) {
            uint2 Bw[3][2];
            #pragma unroll
            for (int gg = 0; gg < 3; ++gg)
                #pragma unroll
                for (int nt = 0; nt < 2; ++nt)
                    Bw[gg][nt] = g_wpack[(8 + kt) * 1536 +
                                 (gg * 16 + 2 * w + nt) * 32 + l];
            unsigned a[2][4];
            #pragma unroll
            for (int mt = 0; mt < 2; ++mt)
                ldsm4(a[mt], hhA + mt * (16 * SMP * 2) + kt * 32);
            #pragma unroll
            for (int gg = 0; gg < 3; ++gg) {
                const int sl = (gg < 2) ? gg : 2;
                #pragma unroll
                for (int nt = 0; nt < 2; ++nt)
                    #pragma unroll
                    for (int mt = 0; mt < 2; ++mt)
                        mma16816(acc[sl][mt][nt], a[mt], Bw[gg][nt]);
            }
        }

        // own cp.async group for gx(t) must be complete before epilogue
        if (t + 1 < LL) asm volatile("cp.async.wait_group 1;" ::: "memory");
        else            asm volatile("cp.async.wait_group 0;" ::: "memory");
        __syncthreads();   // barrier B: GEMM h-reads done; gx(t) visible

        // ---- epilogue(t) ----
        const unsigned short* gxs = ring + s * 32 * GXR;
        #pragma unroll
        for (int mt = 0; mt < 2; ++mt)
            #pragma unroll
            for (int rh = 0; rh < 2; ++rh) {
                int row = mt * 16 + g + rh * 8;
                float p = 0.f;
                #pragma unroll
                for (int nt = 0; nt < 2; ++nt) {
                    int u = (nt ? ub : ua);
                    float wox = nt ? woB.x : woA.x;
                    float woy = nt ? woB.y : woA.y;
                    unsigned gr = *(const unsigned*)&gxs[row * GXR + u];
                    unsigned gz = *(const unsigned*)&gxs[row * GXR + 128 + u];
                    unsigned gn = *(const unsigned*)&gxs[row * GXR + 256 + u];
                    float r0 = sigm(acc[0][mt][nt][rh * 2]     + hlo(gr) + Bs[u]);
                    float r1 = sigm(acc[0][mt][nt][rh * 2 + 1] + hhi(gr) + Bs[u + 1]);
                    float z0 = sigm(acc[1][mt][nt][rh * 2]     + hlo(gz) + Bs[128 + u]);
                    float z1 = sigm(acc[1][mt][nt][rh * 2 + 1] + hhi(gz) + Bs[128 + u + 1]);
                    float n0 = tanh_mufu(hlo(gn) + Bs[256 + u]
                               + r0 * (acc[2][mt][nt][rh * 2]     + Bs[384 + u]));
                    float n1 = tanh_mufu(hhi(gn) + Bs[256 + u + 1]
                               + r1 * (acc[2][mt][nt][rh * 2 + 1] + Bs[384 + u + 1]));
                    unsigned ohv = *(const unsigned*)&hh[row * SMP + u];
                    unsigned olv = *(const unsigned*)&hl[row * SMP + u];
                    float ho0 = hlo(ohv) + hlo(olv);
                    float ho1 = hhi(ohv) + hhi(olv);
                    float hn0 = (1.f - z0) * n0 + z0 * ho0;
                    float hn1 = (1.f - z1) * n1 + z1 * ho1;
                    __half p0 = __float2half_rn(hn0);
                    __half p1 = __float2half_rn(hn1);
                    *(unsigned*)&hh[row * SMP + u] = pkh(p0, p1);
                    *(unsigned*)&hl[row * SMP + u] =
                        pkh(__float2half_rn(hn0 - __half2float(p0)),
                            __float2half_rn(hn1 - __half2float(p1)));
                    p += hn0 * wox + hn1 * woy;
                }
                p += __shfl_xor_sync(0xffffffffu, p, 1);
                p += __shfl_xor_sync(0xffffffffu, p, 2);
                if (tg == 0) outb[w * TN + row] = p;
            }
    }

    __syncthreads();
    if (tid < TN) {
        float sum = bo;
        #pragma unroll
        for (int ww = 0; ww < 8; ++ww) sum += outb[ww * TN + tid];
        out[(size_t)(nBase + tid) * LL + (LL - 1)] = sum;
    }
}

extern "C" void kernel_launch(void* const* d_in, const int* in_sizes, int n_in,
                              void* d_out, int out_size) {
    const float* item  = (const float*)d_in[0];
    const float* user  = (const float*)d_in[1];
    const float* W_ih  = (const float*)d_in[2];
    const float* W_hh  = (const float*)d_in[3];
    const float* b_ih  = (const float*)d_in[4];
    const float* b_hh  = (const float*)d_in[5];
    const float* W_out = (const float*)d_in[6];
    const float* b_out = (const float*)d_in[7];
    float* out = (float*)d_out;

    prep_weights<<<(2 * 8 * 48 * 32 + 255) / 256, 256>>>(W_ih, W_hh);

    size_t smem1 = (size_t)(64 * SMP + 64 * GSTG) * 2;   // 68608 B
    cudaFuncSetAttribute(gx_prepass,
                         cudaFuncAttributeMaxDynamicSharedMemorySize, (int)smem1);
    gx_prepass<<<NL / 64, 512, smem1>>>(item);

    size_t smem2 = (size_t)(2 * TN * SMP + 2 * 32 * GXR) * 2
                 + 8 * TN * sizeof(float) + 512 * sizeof(float);
    // 17408 + 50176 + 1024 + 2048 = 70656 B -> 2 CTAs/SM
    cudaFuncSetAttribute(gru_rec,
                         cudaFuncAttributeMaxDynamicSharedMemorySize, (int)smem2);
    gru_rec<<<NCTA, NTHR, smem2>>>(user, b_ih, b_hh, W_out, b_out, out);
}

// round 17
// speedup vs baseline: 1.5714x; 1.5714x over previous
#include <cuda_runtime.h>
#include <cuda_fp16.h>

// ---------------------------------------------------------------------------
// SlatewiseGRU via tensor cores: mma.sync m16n8k16 fp16, fp32 accumulate.
// R16 = R15 with the header-collision fix (h2tanh -> h2tanh_mufu).
// R12 (best: 195us) + f16x2 epilogue:
//   sigmoid/tanh via tanh.approx.f16x2 (24 MUFU/thread/step vs 48),
//   r/z biases pre-halved (sigma(x) = 0.5 + 0.5 tanh(x/2)),
//   n-gate inner math in half2 (HFMA2), packed cvt for staging/splitting.
// GEMM inputs single fp16 plane (x_hi*W + h_hi*W); h state fp16 hi+lo;
// fp32 convex update. Schedule: TN=32, 256 thr, 2 CTAs/SM, 2 barriers/step.
// ---------------------------------------------------------------------------

#define DD   128
#define LL   32
#define NSEQ 8192
#define TN   32
#define NTHR 256
#define NCTA (NSEQ / TN)   // 256
#define SMP  136           // padded SMEM row stride (fp16 elems); row = 272 B

// Packed B-fragments: [wt:2 (ih,hh)][kt:8][ntile:48 (gg*16+w)][lane:32]
__device__ uint2 g_wpack[2 * 8 * 48 * 32];

__global__ void prep_weights(const float* __restrict__ W_ih,
                             const float* __restrict__ W_hh) {
    int idx = blockIdx.x * blockDim.x + threadIdx.x;
    if (idx >= 2 * 8 * 48 * 32) return;
    int l  = idx & 31;
    int r  = idx >> 5;
    int nt = r % 48; r /= 48;
    int kt = r % 8;  r /= 8;
    int wt = r;
    const float* W = wt ? W_hh : W_ih;
    int gg = nt / 16, w = nt % 16;
    int j  = gg * 128 + w * 8 + (l >> 2);     // gate row (B col n = lane>>2)
    int d0 = kt * 16 + (l & 3) * 2;           // k0 = (lane%4)*2
    unsigned short e[4];
    #pragma unroll
    for (int q = 0; q < 4; ++q) {
        int d = d0 + (q & 1) + (q >> 1) * 8;  // b0:{k0,k0+1}  b1:{k0+8,k0+9}
        e[q] = __half_as_ushort(__float2half_rn(W[j * DD + d]));
    }
    uint2 v;
    v.x = (unsigned)e[0] | ((unsigned)e[1] << 16);
    v.y = (unsigned)e[2] | ((unsigned)e[3] << 16);
    g_wpack[idx] = v;
}

__device__ __forceinline__ unsigned pkh(__half a, __half b) {
    return (unsigned)__half_as_ushort(a) | ((unsigned)__half_as_ushort(b) << 16);
}
__device__ __forceinline__ float hlo(unsigned u) {
    return __half2float(__ushort_as_half((unsigned short)(u & 0xffffu)));
}
__device__ __forceinline__ float hhi(unsigned u) {
    return __half2float(__ushort_as_half((unsigned short)(u >> 16)));
}

__device__ __forceinline__ void mma16816(float* c, const unsigned* a, uint2 b) {
    asm volatile(
        "mma.sync.aligned.m16n8k16.row.col.f32.f16.f16.f32 "
        "{%0,%1,%2,%3}, {%4,%5,%6,%7}, {%8,%9}, {%0,%1,%2,%3};\n"
        : "+f"(c[0]), "+f"(c[1]), "+f"(c[2]), "+f"(c[3])
        : "r"(a[0]), "r"(a[1]), "r"(a[2]), "r"(a[3]), "r"(b.x), "r"(b.y));
}

__device__ __forceinline__ void ldsm4(unsigned* r, unsigned addr) {
    asm volatile("ldmatrix.sync.aligned.m8n8.x4.shared.b16 {%0,%1,%2,%3}, [%4];"
                 : "=r"(r[0]), "=r"(r[1]), "=r"(r[2]), "=r"(r[3]) : "r"(addr));
}

// tanh.approx.f16x2 : one MUFU op for two lanes. (renamed: cuda_fp16.hpp
// already defines a device function named h2tanh)
__device__ __forceinline__ __half2 h2tanh_mufu(__half2 x) {
    unsigned xi = *(unsigned*)&x, yi;
    asm("tanh.approx.f16x2 %0, %1;" : "=r"(yi) : "r"(xi));
    return *(__half2*)&yi;
}

extern __shared__ char smraw[];

__global__ void __launch_bounds__(NTHR, 2)
gru_mma(const float* __restrict__ item,   // [N, L, D]
        const float* __restrict__ user,   // [N, D]
        const float* __restrict__ b_ih,   // [384]
        const float* __restrict__ b_hh,   // [384]
        const float* __restrict__ W_out,  // [128]
        const float* __restrict__ b_out,  // [1]
        float* __restrict__ out)          // [N, L]
{
    unsigned short* xh = (unsigned short*)smraw;      // x, single fp16 plane
    unsigned short* hh = xh + TN * SMP;               // h hi (MMA input)
    unsigned short* hl = hh + TN * SMP;               // h lo (state only)
    float* outb = (float*)(hl + TN * SMP);            // [8][32]
    float* Bs   = outb + 8 * TN;                      // [512]

    const int tid = threadIdx.x;
    const int w   = tid >> 5;   // 8 warps
    const int l   = tid & 31;
    const int g   = l >> 2;
    const int tg  = l & 3;
    const int nBase = blockIdx.x * TN;

    // Biases -> SMEM: [0:256) = 0.5*(b_ih+b_hh) for r,z (pre-halved for the
    // sigma(x)=0.5+0.5*tanh(x/2) path); [256:384) b_ih n; [384:512) b_hh n.
    for (int i = tid; i < 512; i += NTHR) {
        float v;
        if (i < 256)      v = 0.5f * (b_ih[i] + b_hh[i]);
        else if (i < 384) v = b_ih[i];
        else              v = b_hh[i - 128];
        Bs[i] = v;
    }

    // ldmatrix per-thread base addresses
    const int rowsel = l & 15;
    const int halfc  = l >> 4;
    const unsigned lmOff = (unsigned)((rowsel * SMP + halfc * 8) * 2);
    const unsigned xhA = (unsigned)__cvta_generic_to_shared(xh) + lmOff;
    const unsigned hhA = (unsigned)__cvta_generic_to_shared(hh) + lmOff;

    // this thread's output units: two groups of 2, in n8-subtiles nt=0,1
    const int ua = w * 16 + tg * 2;       // nt = 0
    const int ub = ua + 8;                // nt = 1
    float2 woA = *(const float2*)(W_out + ua);
    float2 woB = *(const float2*)(W_out + ub);
    const float bo = b_out[0];

    // h0 = user_embs; owner-thread init (fp16 hi/lo split)
    #pragma unroll
    for (int mt = 0; mt < 2; ++mt)
        #pragma unroll
        for (int rh = 0; rh < 2; ++rh) {
            int row = mt * 16 + g + rh * 8;
            #pragma unroll
            for (int nt = 0; nt < 2; ++nt) {
                int u = (nt ? ub : ua);
                float2 v = *(const float2*)(user + (size_t)(nBase + row) * DD + u);
                __half2 hi2 = __floats2half2_rn(v.x, v.y);
                float2 hif = __half22float2(hi2);
                __half2 lo2 = __floats2half2_rn(v.x - hif.x, v.y - hif.y);
                *(__half2*)&hh[row * SMP + u] = hi2;
                *(__half2*)&hl[row * SMP + u] = lo2;
            }
        }

    // staging coordinates (4 float4 per thread per step: 32 rows x 32 float4)
    int srow[4], scol[4];
    #pragma unroll
    for (int ii = 0; ii < 4; ++ii) {
        int i = tid + ii * NTHR;
        srow[ii] = i >> 5;
        scol[ii] = (i & 31) * 4;
    }

    // prologue: prefetch x_0
    float4 xr[4];
    #pragma unroll
    for (int ii = 0; ii < 4; ++ii)
        xr[ii] = *(const float4*)(item +
                   ((size_t)(nBase + srow[ii]) * LL + 0) * DD + scol[ii]);

    for (int t = 0; t < LL; ++t) {
        // ---- store prefetched x_t into SMEM (single fp16 plane) ----
        #pragma unroll
        for (int ii = 0; ii < 4; ++ii) {
            float4 v = xr[ii];
            uint2 hv;
            __half2 a01 = __floats2half2_rn(v.x, v.y);
            __half2 a23 = __floats2half2_rn(v.z, v.w);
            hv.x = *(unsigned*)&a01;
            hv.y = *(unsigned*)&a23;
            *(uint2*)&xh[srow[ii] * SMP + scol[ii]] = hv;
        }
        __syncthreads();   // x_t, h(t-1) writes, outb(t-1) all visible

        // ---- finish output of step t-1 ----
        if (t > 0 && tid < TN) {
            float s = bo;
            #pragma unroll
            for (int ww = 0; ww < 8; ++ww) s += outb[ww * TN + tid];
            out[(size_t)(nBase + tid) * LL + (t - 1)] = s;
        }

        // acc[slot r,z,nx,nh][mt:2][nt:2][4]
        float acc[4][2][2][4];
        #pragma unroll
        for (int s = 0; s < 4; ++s)
            #pragma unroll
            for (int mt = 0; mt < 2; ++mt)
                #pragma unroll
                for (int nt = 0; nt < 2; ++nt)
                    #pragma unroll
                    for (int q = 0; q < 4; ++q) acc[s][mt][nt][q] = 0.f;

        // ---- GEMM: x-side (1 term) + h-side (1 term), single W plane ----
        #pragma unroll
        for (int kt = 0; kt < 8; ++kt) {       // x-side
            uint2 Bw[3][2];
            #pragma unroll
            for (int gg = 0; gg < 3; ++gg)
                #pragma unroll
                for (int nt = 0; nt < 2; ++nt) {
                    int off = (gg * 16 + 2 * w + nt) * 32 + l;
                    Bw[gg][nt] = g_wpack[kt * 1536 + off];
                }
            unsigned a[2][4];
            #pragma unroll
            for (int mt = 0; mt < 2; ++mt)
                ldsm4(a[mt], xhA + mt * (16 * SMP * 2) + kt * 32);
            #pragma unroll
            for (int gg = 0; gg < 3; ++gg) {
                const int s = (gg < 2) ? gg : 2;
                #pragma unroll
                for (int nt = 0; nt < 2; ++nt)
                    #pragma unroll
                    for (int mt = 0; mt < 2; ++mt)
                        mma16816(acc[s][mt][nt], a[mt], Bw[gg][nt]);
            }
        }
        #pragma unroll
        for (int kt = 0; kt < 8; ++kt) {       // h-side, single plane
            uint2 Bw[3][2];
            #pragma unroll
            for (int gg = 0; gg < 3; ++gg)
                #pragma unroll
                for (int nt = 0; nt < 2; ++nt) {
                    int off = (gg * 16 + 2 * w + nt) * 32 + l;
                    Bw[gg][nt] = g_wpack[(8 + kt) * 1536 + off];
                }
            unsigned a[2][4];
            #pragma unroll
            for (int mt = 0; mt < 2; ++mt)
                ldsm4(a[mt], hhA + mt * (16 * SMP * 2) + kt * 32);
            #pragma unroll
            for (int gg = 0; gg < 3; ++gg) {
                const int s = (gg < 2) ? gg : 3;
                #pragma unroll
                for (int nt = 0; nt < 2; ++nt)
                    #pragma unroll
                    for (int mt = 0; mt < 2; ++mt)
                        mma16816(acc[s][mt][nt], a[mt], Bw[gg][nt]);
            }
        }

        // ---- prefetch x_{t+1} while MMAs drain ----
        if (t < LL - 1) {
            #pragma unroll
            for (int ii = 0; ii < 4; ++ii)
                xr[ii] = *(const float4*)(item +
                           ((size_t)(nBase + srow[ii]) * LL + (t + 1)) * DD + scol[ii]);
        }
        __syncthreads();   // all SMEM A reads complete

        // ---- epilogue: f16x2 gates, fp32 convex update, output partials ----
        const __half2 h05 = __floats2half2_rn(0.5f, 0.5f);
        #pragma unroll
        for (int mt = 0; mt < 2; ++mt)
            #pragma unroll
            for (int rh = 0; rh < 2; ++rh) {
                int row = mt * 16 + g + rh * 8;
                float p = 0.f;
                #pragma unroll
                for (int nt = 0; nt < 2; ++nt) {
                    int u = (nt ? ub : ua);
                    float wox = nt ? woB.x : woA.x;
                    float woy = nt ? woB.y : woA.y;
                    // r gate: 0.5*acc + 0.5*b -> tanh -> r = 0.5t+0.5 (half2)
                    float ar0 = fmaf(acc[0][mt][nt][rh * 2],     0.5f, Bs[u]);
                    float ar1 = fmaf(acc[0][mt][nt][rh * 2 + 1], 0.5f, Bs[u + 1]);
                    __half2 rh2 = __hfma2(h2tanh_mufu(__floats2half2_rn(ar0, ar1)),
                                          h05, h05);
                    // z gate: same path, kept as float2 for the fp32 update
                    float az0 = fmaf(acc[1][mt][nt][rh * 2],     0.5f, Bs[128 + u]);
                    float az1 = fmaf(acc[1][mt][nt][rh * 2 + 1], 0.5f, Bs[128 + u + 1]);
                    float2 ztf = __half22float2(
                        h2tanh_mufu(__floats2half2_rn(az0, az1)));
                    float z0 = fmaf(ztf.x, 0.5f, 0.5f);
                    float z1 = fmaf(ztf.y, 0.5f, 0.5f);
                    // n gate: tanh(axn + r*ahn) in half2
                    float axn0 = acc[2][mt][nt][rh * 2]     + Bs[256 + u];
                    float axn1 = acc[2][mt][nt][rh * 2 + 1] + Bs[256 + u + 1];
                    float ahn0 = acc[3][mt][nt][rh * 2]     + Bs[384 + u];
                    float ahn1 = acc[3][mt][nt][rh * 2 + 1] + Bs[384 + u + 1];
                    __half2 nin = __hfma2(rh2,
                                          __floats2half2_rn(ahn0, ahn1),
                                          __floats2half2_rn(axn0, axn1));
                    float2 nf = __half22float2(h2tanh_mufu(nin));
                    // accurate h_old = hi + lo
                    unsigned ohv = *(const unsigned*)&hh[row * SMP + u];
                    unsigned olv = *(const unsigned*)&hl[row * SMP + u];
                    float ho0 = hlo(ohv) + hlo(olv);
                    float ho1 = hhi(ohv) + hhi(olv);
                    // hn = n + z*(h_old - n)  (fp32)
                    float hn0 = fmaf(z0, ho0 - nf.x, nf.x);
                    float hn1 = fmaf(z1, ho1 - nf.y, nf.y);
                    __half2 hi2 = __floats2half2_rn(hn0, hn1);
                    float2 hif = __half22float2(hi2);
                    __half2 lo2 = __floats2half2_rn(hn0 - hif.x, hn1 - hif.y);
                    *(__half2*)&hh[row * SMP + u] = hi2;
                    *(__half2*)&hl[row * SMP + u] = lo2;
                    p += hn0 * wox + hn1 * woy;
                }
                p += __shfl_xor_sync(0xffffffffu, p, 1);
                p += __shfl_xor_sync(0xffffffffu, p, 2);
                if (tg == 0) outb[w * TN + row] = p;
            }
        // next iteration's first barrier covers outb/h visibility
    }

    __syncthreads();
    if (tid < TN) {
        float s = bo;
        #pragma unroll
        for (int ww = 0; ww < 8; ++ww) s += outb[ww * TN + tid];
        out[(size_t)(nBase + tid) * LL + (LL - 1)] = s;
    }
}

extern "C" void kernel_launch(void* const* d_in, const int* in_sizes, int n_in,
                              void* d_out, int out_size) {
    const float* item  = (const float*)d_in[0];
    const float* user  = (const float*)d_in[1];
    const float* W_ih  = (const float*)d_in[2];
    const float* W_hh  = (const float*)d_in[3];
    const float* b_ih  = (const float*)d_in[4];
    const float* b_hh  = (const float*)d_in[5];
    const float* W_out = (const float*)d_in[6];
    const float* b_out = (const float*)d_in[7];
    float* out = (float*)d_out;

    prep_weights<<<(2 * 8 * 48 * 32 + 255) / 256, 256>>>(W_ih, W_hh);

    size_t smem = (size_t)(3 * TN * SMP) * sizeof(unsigned short)  // x + h(hi,lo)
                + 8 * TN * sizeof(float)        // outb
                + 512 * sizeof(float);          // biases
    // 26112 + 1024 + 2048 = 29184 B per CTA -> 58368 B per SM at 2 CTAs
    cudaFuncSetAttribute(gru_mma,
                         cudaFuncAttributeMaxDynamicSharedMemorySize, (int)smem);
    gru_mma<<<NCTA, NTHR, smem>>>(item, user, b_ih, b_hh, W_out, b_out, out);
}